// round 15
// baseline (speedup 1.0000x reference)
#include <cuda_runtime.h>
#include <math.h>

#define TMAX 64
#define TPAD 68   // TMAX + 4 pad slots for the x4-unrolled loops

// ANCHORS/stride per layer (exact: divisors are powers of two, bit-identical to fdiv)
__constant__ float c_allg[3][18] = {
  {0.3125f,0.40625f, 0.5f,0.9375f, 1.03125f,0.71875f, 0.9375f,1.90625f, 1.9375f,1.40625f,
   1.84375f,3.71875f, 3.625f,2.8125f, 4.875f,6.1875f, 11.65625f,10.1875f},
  {0.625f,0.8125f, 1.0f,1.875f, 2.0625f,1.4375f, 1.875f,3.8125f, 3.875f,2.8125f,
   3.6875f,7.4375f, 7.25f,5.625f, 9.75f,12.375f, 23.3125f,20.375f},
  {1.25f,1.625f, 2.0f,3.75f, 4.125f,2.875f, 3.75f,7.625f, 7.75f,5.625f,
   7.375f,14.875f, 14.5f,11.25f, 19.5f,24.75f, 46.625f,40.75f}
};

__device__ double   g_acc   = 0.0;
__device__ unsigned g_count = 0u;

__device__ __forceinline__ float slog(float x) { return x > 0.f ? __logf(x) : -100.f; }
__device__ __forceinline__ float sigm(float x) { return 1.f/(1.f + __expf(-x)); }

// Single fused kernel. 128 threads/block, 1 cell/thread.
// 1D grid: bx = chunk*16 + batch (batch fastest -> round-robin balance).
// Threads 0-63 preprocess targets into smem (overlapped with main LDGs).
// NEW: block-level conservative target cull — the block's 128 predicted
// boxes are reduced to a bbox + min(ca); warp 0 pre-filters targets with a
// provably-conservative bound, so the hot ignore loop runs only survivors.
// Class-BCE epilogue stays warp-cooperative.
__global__ __launch_bounds__(128)
void k_loss(const float* __restrict__ r0, const float* __restrict__ r1,
            const float* __restrict__ r2, const float* __restrict__ tg,
            int T,
            int HW0, int W0, int HW1, int W1, int HW2, int W2,
            int nc0, int nc01, float* __restrict__ out)
{
    __shared__ float4 sbox[TPAD];                 // all valid targets
    __shared__ __align__(16) float sarea[TPAD];   // 0.7 * target area
    __shared__ float4 scbox[TPAD];                // culled (surviving) targets
    __shared__ __align__(16) float scarea[TPAD];
    __shared__ __align__(16) int   skey[TPAD];    // compacted assigned keys
    __shared__ float4 sext4[TMAX];                // fx,fy,log(w/aw),log(h/ah)
    __shared__ float2 sext2[TMAX];                // scale, cls
    __shared__ int    s_cnt2[2], s_kc2[2];
    __shared__ int    scnt, skcnt, sccnt;
    __shared__ float  s_red[4][5];                // per-warp bbox/camin partials
    __shared__ float  swsum[4];

    int bx    = blockIdx.x;
    int b     = bx & 15;
    int chunk = bx >> 4;

    int layer; const float* raw; int HW, W, base;
    if (chunk < nc0)       { layer = 0; raw = r0; HW = HW0; W = W0; base = 0;    }
    else if (chunk < nc01) { layer = 1; raw = r1; HW = HW1; W = W1; base = nc0;  }
    else                   { layer = 2; raw = r2; HW = HW2; W = W2; base = nc01; }

    int tid = threadIdx.x;
    int lane = tid & 31, wid = tid >> 5;
    int fs  = W;
    float fsf = (float)fs;
    int group = 2 - layer;

    // ---- cell decode + ISSUE main global loads first ----
    int cell = (chunk - base)*128 + tid;
    bool live = cell < 3*HW;
    int a = 0, h = 0, w = 0;
    float o0 = 0.f, o1 = 0.f, o2 = 0.f, o3 = 0.f, o4 = 0.f;
    const float* p = raw;
    if (live) {
        float invHW = 1.f/(float)HW, invW = 1.f/(float)W;
        a = (int)((float)cell * invHW);
        int hw = cell - a*HW;
        if (hw < 0)        { a--; hw += HW; }
        else if (hw >= HW) { a++; hw -= HW; }
        h = (int)((float)hw * invW);
        w = hw - h*W;
        if (w < 0)       { h--; w += W; }
        else if (w >= W) { h++; w -= W; }
        p = raw + ((size_t)b*255 + (size_t)a*85)*(size_t)HW + hw;
        o0 = __ldg(p);
        o1 = __ldg(p + HW);
        o2 = __ldg(p + 2*HW);
        o3 = __ldg(p + 3*HW);
        o4 = __ldg(p + 4*HW);
    }

    // ---- phase 1a: target load + valid compaction indices (threads 0..63) ----
    bool valid = false;
    float cf = 0.f, tx = 0.f, ty = 0.f, tw = 0.f, th = 0.f;
    int pre = 0;
    if (tid < 64) {
        if (tid < T) {
            const float* L = tg + ((size_t)b*T + tid)*5;
            cf = L[0];
            float x = L[1], y = L[2], ww = L[3], hh = L[4];
            valid = (cf + x + y + ww + hh) > 0.f;
            tx = x*fsf; ty = y*fsf; tw = ww*fsf; th = hh*fsf;
        }
        unsigned ball = __ballot_sync(0xffffffffu, valid);
        pre = __popc(ball & ((1u << lane) - 1u));
        if (lane == 0) s_cnt2[wid] = __popc(ball);
    }
    __syncthreads();

    // ---- phase 1b: anchor argmax + box/key production (threads 0..63) ----
    int key = -1; int bn = 0, gi = 0, gj = 0; float twth = 0.f;
    int kpre = 0;
    if (tid < 64) {
        if (tid >= 32) pre += s_cnt2[0];
        int total = s_cnt2[0] + s_cnt2[1];
        if (valid) {
            twth = tw*th;
            // argmax over 9 anchor IoUs (first max wins)
            float best = -1.f; int bi = 0;
            #pragma unroll
            for (int i = 0; i < 9; ++i) {
                float aw = c_allg[layer][2*i], ah = c_allg[layer][2*i+1];
                float mw = fminf(tw, aw), mh = fminf(th, ah);
                float inter = (mw > 0.f && mh > 0.f) ? mw*mh : 0.f;
                float iou = inter / (twth + aw*ah - inter);
                if (iou > best) { best = iou; bi = i; }
            }
            bn = bi - (bi/3)*3;
            sbox[pre]  = make_float4(tx - 0.5f*tw, ty - 0.5f*th,
                                     tx + 0.5f*tw, ty + 0.5f*th);
            sarea[pre] = 0.7f*twth;
            if ((bi/3) == group) {
                gi = (int)tx; gj = (int)ty;
                if (gi >= 0 && gi < fs && gj >= 0 && gj < fs)   // mode='drop'
                    key = (bn << 28) | (gj << 14) | gi;
            }
        }
        unsigned kb = __ballot_sync(0xffffffffu, key >= 0);
        kpre = __popc(kb & ((1u << lane) - 1u));
        if (lane == 0) s_kc2[wid] = __popc(kb);
        if (tid == 0) scnt = total;
    }
    __syncthreads();

    // ---- phase 1c: key-side data (threads 0..63) + geometry (all threads) ----
    if (tid < 64) {
        if (tid >= 32) kpre += s_kc2[0];
        int ktotal = s_kc2[0] + s_kc2[1];
        if (key >= 0) {
            skey[kpre] = key;
            float aw = c_allg[layer][2*(3*group + bn)];
            float ah = c_allg[layer][2*(3*group + bn) + 1];
            sext4[kpre] = make_float4(tx - (float)gi, ty - (float)gj,
                                      logf(tw/aw + 1e-16f), logf(th/ah + 1e-16f));
            sext2[kpre] = make_float2(sqrtf(2.f - twth/(fsf*fsf)),
                                      __int_as_float((int)cf));
        }
        if (tid >= 32 && tid < 36) skey[ktotal + (tid - 32)] = -1;  // key pads
        if (tid == 0) skcnt = ktotal;
    }

    // per-cell geometry (main LDGs have landed); sentinels for dead lanes
    float s0 = 0.f, s1 = 0.f;
    float atlx = 1e30f, atly = 1e30f, abrx = -1e30f, abry = -1e30f;
    float ca = 0.f, car = 1e30f;
    int ckey = -2;
    if (live) {
        s0 = sigm(o0); s1 = sigm(o1);
        float maw = c_allg[layer][2*(3*group + a)];
        float mah = c_allg[layer][2*(3*group + a) + 1];
        float pw = __expf(o2)*maw, ph = __expf(o3)*mah;
        float px = s0 + (float)w, py = s1 + (float)h;
        atlx = px - 0.5f*pw;  atly = py - 0.5f*ph;
        abrx = px + 0.5f*pw;  abry = py + 0.5f*ph;
        ca   = 0.7f*(pw*ph);  car = ca;
        ckey = (a << 28) | (h << 14) | w;
    }
    // warp-level reduce of block bbox + min(ca)
    {
        float v0 = atlx, v1 = atly, v2 = abrx, v3 = abry, v4 = car;
        #pragma unroll
        for (int off = 16; off; off >>= 1) {
            v0 = fminf(v0, __shfl_xor_sync(0xffffffffu, v0, off));
            v1 = fminf(v1, __shfl_xor_sync(0xffffffffu, v1, off));
            v2 = fmaxf(v2, __shfl_xor_sync(0xffffffffu, v2, off));
            v3 = fmaxf(v3, __shfl_xor_sync(0xffffffffu, v3, off));
            v4 = fminf(v4, __shfl_xor_sync(0xffffffffu, v4, off));
        }
        if (lane == 0) {
            s_red[wid][0] = v0; s_red[wid][1] = v1; s_red[wid][2] = v2;
            s_red[wid][3] = v3; s_red[wid][4] = v4;
        }
    }
    __syncthreads();

    // combine per-warp partials (every thread computes its own copy)
    float bxmin = fminf(fminf(s_red[0][0], s_red[1][0]), fminf(s_red[2][0], s_red[3][0]));
    float bymin = fminf(fminf(s_red[0][1], s_red[1][1]), fminf(s_red[2][1], s_red[3][1]));
    float bxmax = fmaxf(fmaxf(s_red[0][2], s_red[1][2]), fmaxf(s_red[2][2], s_red[3][2]));
    float bymax = fmaxf(fmaxf(s_red[0][3], s_red[1][3]), fmaxf(s_red[2][3], s_red[3][3]));
    float cmin  = fminf(fminf(s_red[0][4], s_red[1][4]), fminf(s_red[2][4], s_red[3][4]));

    // ---- conservative target cull + compaction (warp 0 only) ----
    if (tid < 32) {
        int cnt = scnt;
        // first 32 targets
        bool k0 = false; float4 bb0; float ar0 = 0.f;
        if (tid < cnt) {
            bb0 = sbox[tid]; ar0 = sarea[tid];
            float ixu = fminf(bxmax, bb0.z) - fmaxf(bxmin, bb0.x);
            float iyu = fminf(bymax, bb0.w) - fmaxf(bymin, bb0.y);
            float bnd = fminf(fminf(ixu, iyu), fmaf(1.7f, ixu*iyu, -cmin) - ar0);
            k0 = bnd > 0.f;
        }
        unsigned c0 = __ballot_sync(0xffffffffu, k0);
        int pos0 = __popc(c0 & ((1u << lane) - 1u));
        if (k0) { scbox[pos0] = bb0; scarea[pos0] = ar0; }
        int n0 = __popc(c0);
        // second 32 targets
        bool k1 = false; float4 bb1; float ar1 = 0.f;
        int t1 = tid + 32;
        if (t1 < cnt) {
            bb1 = sbox[t1]; ar1 = sarea[t1];
            float ixu = fminf(bxmax, bb1.z) - fmaxf(bxmin, bb1.x);
            float iyu = fminf(bymax, bb1.w) - fmaxf(bymin, bb1.y);
            float bnd = fminf(fminf(ixu, iyu), fmaf(1.7f, ixu*iyu, -cmin) - ar1);
            k1 = bnd > 0.f;
        }
        unsigned c1 = __ballot_sync(0xffffffffu, k1);
        int pos1 = n0 + __popc(c1 & ((1u << lane) - 1u));
        if (k1) { scbox[pos1] = bb1; scarea[pos1] = ar1; }
        int cc = n0 + __popc(c1);
        if (lane < 4) {   // inert pads for the x4 unroll
            scbox[cc + lane]  = make_float4(2e9f, 2e9f, -2e9f, -2e9f);
            scarea[cc + lane] = 0.f;
        }
        if (lane == 0) sccnt = cc;
    }
    __syncthreads();

    // ---- phase 2: per-cell loss ----
    float lsum = 0.f;
    int tmi = -1;
    if (live) {
        float s4 = sigm(o4);

        // ignore test over SURVIVING targets (order-free max combiner):
        // piou > 0.7  <=>  ix>0 & iy>0 & 1.7*ai - 0.7*(A+B) > 0
        float anyf = -1e30f;
        const float4* scarea4 = (const float4*)scarea;
        int cnt4 = (sccnt + 3) & ~3;
        for (int t = 0; t < cnt4; t += 4) {
            float4 b0 = scbox[t], b1 = scbox[t+1], b2 = scbox[t+2], b3 = scbox[t+3];
            float4 ar = scarea4[t >> 2];
            {
                float ix = fminf(abrx, b0.z) - fmaxf(atlx, b0.x);
                float iy = fminf(abry, b0.w) - fmaxf(atly, b0.y);
                float lhs = fmaf(1.7f, ix*iy, -ca) - ar.x;
                anyf = fmaxf(anyf, fminf(fminf(ix, iy), lhs));
            }
            {
                float ix = fminf(abrx, b1.z) - fmaxf(atlx, b1.x);
                float iy = fminf(abry, b1.w) - fmaxf(atly, b1.y);
                float lhs = fmaf(1.7f, ix*iy, -ca) - ar.y;
                anyf = fmaxf(anyf, fminf(fminf(ix, iy), lhs));
            }
            {
                float ix = fminf(abrx, b2.z) - fmaxf(atlx, b2.x);
                float iy = fminf(abry, b2.w) - fmaxf(atly, b2.y);
                float lhs = fmaf(1.7f, ix*iy, -ca) - ar.z;
                anyf = fmaxf(anyf, fminf(fminf(ix, iy), lhs));
            }
            {
                float ix = fminf(abrx, b3.z) - fmaxf(atlx, b3.x);
                float iy = fminf(abry, b3.w) - fmaxf(atly, b3.y);
                float lhs = fmaf(1.7f, ix*iy, -ca) - ar.w;
                anyf = fmaxf(anyf, fminf(fminf(ix, iy), lhs));
            }
        }

        // assigned-cell match over compacted key list (last match wins)
        const int4* skey4 = (const int4*)skey;
        int kcnt4 = (skcnt + 3) & ~3;
        for (int t = 0; t < kcnt4; t += 4) {
            int4 k = skey4[t >> 2];
            tmi = (k.x == ckey) ? t   : tmi;
            tmi = (k.y == ckey) ? t+1 : tmi;
            tmi = (k.z == ckey) ? t+2 : tmi;
            tmi = (k.w == ckey) ? t+3 : tmi;
        }

        if (tmi >= 0) {
            // owner-lane terms (cheap); class BCE handled warp-cooperatively below
            float4 e4 = sext4[tmi];
            float2 e2 = sext2[tmi];
            float ts2 = e2.x*e2.x;
            // BCE(xy) weighted by scale^2
            lsum -= ts2*( e4.x*slog(s0) + (1.f - e4.x)*slog(1.f - s0)
                        + e4.y*slog(s1) + (1.f - e4.y)*slog(1.f - s1) );
            // 0.5 * scale^2 * (wh diff)^2
            float dw = o2 - e4.z, dh = o3 - e4.w;
            lsum += 0.5f*ts2*(dw*dw + dh*dh);
            // obj BCE, target 1 (obj_mask forced to 1 at assigned cells)
            lsum -= slog(s4);
        } else if (!(anyf > 0.f)) {
            // obj BCE, target 0 where obj_mask = 1
            lsum -= slog(1.f - s4);
        }
        // (ignored && not assigned) -> obj_mask = 0 -> zero contribution
    }

    // ---- warp-cooperative class BCE for each assigned cell in this warp ----
    {
        unsigned am = __ballot_sync(0xffffffffu, tmi >= 0);
        while (am) {
            int src = __ffs(am) - 1;
            am &= am - 1;
            int stmi = __shfl_sync(0xffffffffu, tmi, src);
            unsigned long long sp =
                __shfl_sync(0xffffffffu, (unsigned long long)p, src);
            const float* cp = (const float*)sp;
            int cls = __float_as_int(sext2[stmi].y);
            float part = 0.f;
            // lanes cover channels c = lane, lane+32, lane+64 (80 total)
            #pragma unroll
            for (int cc = 0; cc < 3; ++cc) {
                int c = lane + cc*32;
                if (c < 80) {
                    float scc = sigm(__ldg(cp + (size_t)(5 + c)*HW));
                    part -= (c == cls) ? slog(scc) : slog(1.f - scc);
                }
            }
            lsum += part;   // any lane may hold it: block reduction sums all
        }
    }

    // ---- phase 3: block reduction + one atomic; globally-last block writes ----
    #pragma unroll
    for (int off = 16; off; off >>= 1)
        lsum += __shfl_xor_sync(0xffffffffu, lsum, off);
    if (lane == 0) swsum[wid] = lsum;
    __syncthreads();
    if (tid == 0) {
        double bsum = (double)swsum[0] + (double)swsum[1]
                    + (double)swsum[2] + (double)swsum[3];
        atomicAdd(&g_acc, bsum);
        __threadfence();
        unsigned prev = atomicAdd(&g_count, 1u);
        if (prev == gridDim.x - 1u) {
            out[0] = (float)g_acc;
            g_acc = 0.0;       // reset for next graph replay
            g_count = 0u;
        }
    }
}

extern "C" void kernel_launch(void* const* d_in, const int* in_sizes, int n_in,
                              void* d_out, int out_size)
{
    const float* r0 = (const float*)d_in[0];
    const float* r1 = (const float*)d_in[1];
    const float* r2 = (const float*)d_in[2];
    const float* targets = (const float*)d_in[3];
    const int B = 16;
    int T = in_sizes[3] / (B*5);
    if (T > TMAX) T = TMAX;

    int HW0 = in_sizes[0] / (B*255);
    int HW1 = in_sizes[1] / (B*255);
    int HW2 = in_sizes[2] / (B*255);
    int W0 = (int)(sqrt((double)HW0) + 0.5);
    int W1 = (int)(sqrt((double)HW1) + 0.5);
    int W2 = (int)(sqrt((double)HW2) + 0.5);

    int nc0 = (3*HW0 + 127)/128;
    int nc1 = (3*HW1 + 127)/128;
    int nc2 = (3*HW2 + 127)/128;
    int nblocks = (nc0 + nc1 + nc2) * 16;
    k_loss<<<nblocks, 128>>>(r0, r1, r2, targets, T,
                             HW0, W0, HW1, W1, HW2, W2,
                             nc0, nc0 + nc1, (float*)d_out);
}

// round 16
// speedup vs baseline: 1.1364x; 1.1364x over previous
#include <cuda_runtime.h>
#include <math.h>

#define TMAX 64
#define TPAD 68   // TMAX + 4 pad slots for the x4-unrolled loops

// ANCHORS/stride per layer (exact: divisors are powers of two, bit-identical to fdiv)
__constant__ float c_allg[3][18] = {
  {0.3125f,0.40625f, 0.5f,0.9375f, 1.03125f,0.71875f, 0.9375f,1.90625f, 1.9375f,1.40625f,
   1.84375f,3.71875f, 3.625f,2.8125f, 4.875f,6.1875f, 11.65625f,10.1875f},
  {0.625f,0.8125f, 1.0f,1.875f, 2.0625f,1.4375f, 1.875f,3.8125f, 3.875f,2.8125f,
   3.6875f,7.4375f, 7.25f,5.625f, 9.75f,12.375f, 23.3125f,20.375f},
  {1.25f,1.625f, 2.0f,3.75f, 4.125f,2.875f, 3.75f,7.625f, 7.75f,5.625f,
   7.375f,14.875f, 14.5f,11.25f, 19.5f,24.75f, 46.625f,40.75f}
};
// aw*ah per anchor per layer (exactly representable; == float product in reference)
__constant__ float c_awh[3][9] = {
  {0.126953125f, 0.46875f, 0.7412109375f, 1.787109375f, 2.724609375f,
   6.8564453125f, 10.1953125f, 30.1640625f, 118.748046875f},
  {0.5078125f, 1.875f, 2.96484375f, 7.1484375f, 10.8984375f,
   27.42578125f, 40.78125f, 120.65625f, 474.9921875f},
  {2.03125f, 7.5f, 11.859375f, 28.59375f, 43.59375f,
   109.703125f, 163.125f, 482.625f, 1899.96875f}
};

__device__ double   g_acc   = 0.0;
__device__ unsigned g_count = 0u;

__device__ __forceinline__ float slog(float x) { return x > 0.f ? __logf(x) : -100.f; }
__device__ __forceinline__ float sigm(float x) { return 1.f/(1.f + __expf(-x)); }

// Single fused kernel. 128 threads/block, 1 cell/thread.
// 1D grid: bx = chunk*16 + batch (batch fastest -> round-robin balance).
// Threads 0-63 preprocess targets into smem (overlapped with main LDGs).
// Anchor argmax is DIVISION-FREE (cross-multiplied IoU comparison).
// Class-BCE epilogue is warp-cooperative (R14 win).
__global__ __launch_bounds__(128)
void k_loss(const float* __restrict__ r0, const float* __restrict__ r1,
            const float* __restrict__ r2, const float* __restrict__ tg,
            int T,
            int HW0, int W0, int HW1, int W1, int HW2, int W2,
            int nc0, int nc01, float* __restrict__ out)
{
    __shared__ float4 sbox[TPAD];                 // target tl.x,tl.y,br.x,br.y
    __shared__ __align__(16) float sarea[TPAD];   // 0.7 * target area
    __shared__ __align__(16) int   skey[TPAD];    // compacted assigned keys
    __shared__ float4 sext4[TMAX];                // fx,fy,log(w/aw),log(h/ah)
    __shared__ float2 sext2[TMAX];                // scale, cls
    __shared__ int    s_cnt2[2], s_kc2[2];
    __shared__ int    scnt, skcnt;
    __shared__ float  swsum[4];

    int bx    = blockIdx.x;
    int b     = bx & 15;
    int chunk = bx >> 4;

    int layer; const float* raw; int HW, W, base;
    if (chunk < nc0)       { layer = 0; raw = r0; HW = HW0; W = W0; base = 0;    }
    else if (chunk < nc01) { layer = 1; raw = r1; HW = HW1; W = W1; base = nc0;  }
    else                   { layer = 2; raw = r2; HW = HW2; W = W2; base = nc01; }

    int tid = threadIdx.x;
    int lane = tid & 31, wid = tid >> 5;
    int fs  = W;
    float fsf = (float)fs;
    int group = 2 - layer;

    // ---- cell decode + ISSUE main global loads first ----
    int cell = (chunk - base)*128 + tid;
    bool live = cell < 3*HW;
    int a = 0, h = 0, w = 0;
    float o0 = 0.f, o1 = 0.f, o2 = 0.f, o3 = 0.f, o4 = 0.f;
    const float* p = raw;
    if (live) {
        float invHW = 1.f/(float)HW, invW = 1.f/(float)W;
        a = (int)((float)cell * invHW);
        int hw = cell - a*HW;
        if (hw < 0)        { a--; hw += HW; }
        else if (hw >= HW) { a++; hw -= HW; }
        h = (int)((float)hw * invW);
        w = hw - h*W;
        if (w < 0)       { h--; w += W; }
        else if (w >= W) { h++; w -= W; }
        p = raw + ((size_t)b*255 + (size_t)a*85)*(size_t)HW + hw;
        o0 = __ldg(p);
        o1 = __ldg(p + HW);
        o2 = __ldg(p + 2*HW);
        o3 = __ldg(p + 3*HW);
        o4 = __ldg(p + 4*HW);
    }

    // ---- phase 1: target preprocessing (threads 0..63) ----
    bool valid = false;
    float cf = 0.f, tx = 0.f, ty = 0.f, tw = 0.f, th = 0.f;
    int pre = 0;
    if (tid < 64) {
        if (tid < T) {
            const float* L = tg + ((size_t)b*T + tid)*5;
            cf = L[0];
            float x = L[1], y = L[2], ww = L[3], hh = L[4];
            valid = (cf + x + y + ww + hh) > 0.f;
            tx = x*fsf; ty = y*fsf; tw = ww*fsf; th = hh*fsf;
        }
        unsigned ball = __ballot_sync(0xffffffffu, valid);
        pre = __popc(ball & ((1u << lane) - 1u));
        if (lane == 0) s_cnt2[wid] = __popc(ball);
    }
    __syncthreads();

    int key = -1; int bn = 0, gi = 0, gj = 0; float twth = 0.f;
    int kpre = 0;
    if (tid < 64) {
        if (tid >= 32) pre += s_cnt2[0];
        int total = s_cnt2[0] + s_cnt2[1];
        if (valid) {
            twth = tw*th;
            // DIVISION-FREE argmax over 9 anchor IoUs (first max wins):
            // iou_i > iou_best  <=>  inter_i*den_best > inter_best*den_i
            // (den > 0 always; best initialized to iou=0 -> first positive wins,
            //  all-zero case keeps bi=0, matching jnp.argmax)
            float bin = 0.f, bde = 1.f; int bi = 0;
            #pragma unroll
            for (int i = 0; i < 9; ++i) {
                float aw = c_allg[layer][2*i], ah = c_allg[layer][2*i+1];
                float mw = fminf(tw, aw), mh = fminf(th, ah);
                float inter = (mw > 0.f && mh > 0.f) ? mw*mh : 0.f;
                float den = twth + c_awh[layer][i] - inter;
                if (inter*bde > bin*den) { bin = inter; bde = den; bi = i; }
            }
            bn = bi - (bi/3)*3;
            sbox[pre]  = make_float4(tx - 0.5f*tw, ty - 0.5f*th,
                                     tx + 0.5f*tw, ty + 0.5f*th);
            sarea[pre] = 0.7f*twth;
            if ((bi/3) == group) {
                gi = (int)tx; gj = (int)ty;
                if (gi >= 0 && gi < fs && gj >= 0 && gj < fs)   // mode='drop'
                    key = (bn << 28) | (gj << 14) | gi;
            }
        }
        unsigned kb = __ballot_sync(0xffffffffu, key >= 0);
        kpre = __popc(kb & ((1u << lane) - 1u));
        if (lane == 0) s_kc2[wid] = __popc(kb);
        // inert box pads
        if (tid >= 32 && tid < 36) {
            int i = total + (tid - 32);
            sbox[i]  = make_float4(2e9f, 2e9f, -2e9f, -2e9f);
            sarea[i] = 0.f;
        }
        if (tid == 0) scnt = total;
    }
    __syncthreads();

    if (tid < 64) {
        if (tid >= 32) kpre += s_kc2[0];
        int ktotal = s_kc2[0] + s_kc2[1];
        if (key >= 0) {
            skey[kpre] = key;
            float aw = c_allg[layer][2*(3*group + bn)];
            float ah = c_allg[layer][2*(3*group + bn) + 1];
            sext4[kpre] = make_float4(tx - (float)gi, ty - (float)gj,
                                      logf(tw/aw + 1e-16f), logf(th/ah + 1e-16f));
            sext2[kpre] = make_float2(sqrtf(2.f - twth/(fsf*fsf)),
                                      __int_as_float((int)cf));
        }
        if (tid >= 32 && tid < 36) skey[ktotal + (tid - 32)] = -1;  // key pads
        if (tid == 0) skcnt = ktotal;
    }
    __syncthreads();

    // ---- phase 2: per-cell loss ----
    float lsum = 0.f;
    int tmi = -1;
    if (live) {
        float s0 = sigm(o0), s1 = sigm(o1), s4 = sigm(o4);
        float maw = c_allg[layer][2*(3*group + a)];
        float mah = c_allg[layer][2*(3*group + a) + 1];
        float pw = __expf(o2)*maw, ph = __expf(o3)*mah;
        float px = s0 + (float)w, py = s1 + (float)h;
        float atlx = px - 0.5f*pw, atly = py - 0.5f*ph;
        float abrx = px + 0.5f*pw, abry = py + 0.5f*ph;
        float ca = 0.7f*(pw*ph);
        int ckey = (a << 28) | (h << 14) | w;

        // ignore test: piou > 0.7  <=>  ix>0 & iy>0 & 1.7*ai - 0.7*(A+B) > 0
        float anyf = -1e30f;
        const float4* sarea4 = (const float4*)sarea;
        int cnt4 = (scnt + 3) & ~3;
        for (int t = 0; t < cnt4; t += 4) {
            float4 b0 = sbox[t], b1 = sbox[t+1], b2 = sbox[t+2], b3 = sbox[t+3];
            float4 ar = sarea4[t >> 2];
            {
                float ix = fminf(abrx, b0.z) - fmaxf(atlx, b0.x);
                float iy = fminf(abry, b0.w) - fmaxf(atly, b0.y);
                float lhs = fmaf(1.7f, ix*iy, -ca) - ar.x;
                anyf = fmaxf(anyf, fminf(fminf(ix, iy), lhs));
            }
            {
                float ix = fminf(abrx, b1.z) - fmaxf(atlx, b1.x);
                float iy = fminf(abry, b1.w) - fmaxf(atly, b1.y);
                float lhs = fmaf(1.7f, ix*iy, -ca) - ar.y;
                anyf = fmaxf(anyf, fminf(fminf(ix, iy), lhs));
            }
            {
                float ix = fminf(abrx, b2.z) - fmaxf(atlx, b2.x);
                float iy = fminf(abry, b2.w) - fmaxf(atly, b2.y);
                float lhs = fmaf(1.7f, ix*iy, -ca) - ar.z;
                anyf = fmaxf(anyf, fminf(fminf(ix, iy), lhs));
            }
            {
                float ix = fminf(abrx, b3.z) - fmaxf(atlx, b3.x);
                float iy = fminf(abry, b3.w) - fmaxf(atly, b3.y);
                float lhs = fmaf(1.7f, ix*iy, -ca) - ar.w;
                anyf = fmaxf(anyf, fminf(fminf(ix, iy), lhs));
            }
        }

        // assigned-cell match over compacted key list (last match wins)
        const int4* skey4 = (const int4*)skey;
        int kcnt4 = (skcnt + 3) & ~3;
        for (int t = 0; t < kcnt4; t += 4) {
            int4 k = skey4[t >> 2];
            tmi = (k.x == ckey) ? t   : tmi;
            tmi = (k.y == ckey) ? t+1 : tmi;
            tmi = (k.z == ckey) ? t+2 : tmi;
            tmi = (k.w == ckey) ? t+3 : tmi;
        }

        if (tmi >= 0) {
            // owner-lane terms (cheap); class BCE handled warp-cooperatively below
            float4 e4 = sext4[tmi];
            float2 e2 = sext2[tmi];
            float ts2 = e2.x*e2.x;
            // BCE(xy) weighted by scale^2
            lsum -= ts2*( e4.x*slog(s0) + (1.f - e4.x)*slog(1.f - s0)
                        + e4.y*slog(s1) + (1.f - e4.y)*slog(1.f - s1) );
            // 0.5 * scale^2 * (wh diff)^2
            float dw = o2 - e4.z, dh = o3 - e4.w;
            lsum += 0.5f*ts2*(dw*dw + dh*dh);
            // obj BCE, target 1 (obj_mask forced to 1 at assigned cells)
            lsum -= slog(s4);
        } else if (!(anyf > 0.f)) {
            // obj BCE, target 0 where obj_mask = 1
            lsum -= slog(1.f - s4);
        }
        // (ignored && not assigned) -> obj_mask = 0 -> zero contribution
    }

    // ---- warp-cooperative class BCE for each assigned cell in this warp ----
    {
        unsigned am = __ballot_sync(0xffffffffu, tmi >= 0);
        while (am) {
            int src = __ffs(am) - 1;
            am &= am - 1;
            int stmi = __shfl_sync(0xffffffffu, tmi, src);
            unsigned long long sp =
                __shfl_sync(0xffffffffu, (unsigned long long)p, src);
            const float* cp = (const float*)sp;
            int cls = __float_as_int(sext2[stmi].y);
            float part = 0.f;
            // lanes cover channels c = lane, lane+32, lane+64 (80 total)
            #pragma unroll
            for (int cc = 0; cc < 3; ++cc) {
                int c = lane + cc*32;
                if (c < 80) {
                    float scc = sigm(__ldg(cp + (size_t)(5 + c)*HW));
                    part -= (c == cls) ? slog(scc) : slog(1.f - scc);
                }
            }
            lsum += part;   // any lane may hold it: block reduction sums all
        }
    }

    // ---- phase 3: block reduction + one atomic; globally-last block writes ----
    #pragma unroll
    for (int off = 16; off; off >>= 1)
        lsum += __shfl_xor_sync(0xffffffffu, lsum, off);
    if (lane == 0) swsum[wid] = lsum;
    __syncthreads();
    if (tid == 0) {
        double bsum = (double)swsum[0] + (double)swsum[1]
                    + (double)swsum[2] + (double)swsum[3];
        atomicAdd(&g_acc, bsum);
        __threadfence();
        unsigned prev = atomicAdd(&g_count, 1u);
        if (prev == gridDim.x - 1u) {
            out[0] = (float)g_acc;
            g_acc = 0.0;       // reset for next graph replay
            g_count = 0u;
        }
    }
}

extern "C" void kernel_launch(void* const* d_in, const int* in_sizes, int n_in,
                              void* d_out, int out_size)
{
    const float* r0 = (const float*)d_in[0];
    const float* r1 = (const float*)d_in[1];
    const float* r2 = (const float*)d_in[2];
    const float* targets = (const float*)d_in[3];
    const int B = 16;
    int T = in_sizes[3] / (B*5);
    if (T > TMAX) T = TMAX;

    int HW0 = in_sizes[0] / (B*255);
    int HW1 = in_sizes[1] / (B*255);
    int HW2 = in_sizes[2] / (B*255);
    int W0 = (int)(sqrt((double)HW0) + 0.5);
    int W1 = (int)(sqrt((double)HW1) + 0.5);
    int W2 = (int)(sqrt((double)HW2) + 0.5);

    int nc0 = (3*HW0 + 127)/128;
    int nc1 = (3*HW1 + 127)/128;
    int nc2 = (3*HW2 + 127)/128;
    int nblocks = (nc0 + nc1 + nc2) * 16;
    k_loss<<<nblocks, 128>>>(r0, r1, r2, targets, T,
                             HW0, W0, HW1, W1, HW2, W2,
                             nc0, nc0 + nc1, (float*)d_out);
}